// round 10
// baseline (speedup 1.0000x reference)
#include <cuda_runtime.h>

#define H    4096
#define IN   512
#define OUT  64
#define NJ4  (H / 4)       // 1024 float4 columns total
#define NB   512           // blocks; <= 592 (148 SM x 4) -> all co-resident
#define NCH  4             // column chunks
#define WF4  (NJ4 / NCH)   // 256 float4 columns per chunk
#define NPH  (2 * NCH)     // grid barriers used

// Device-global scratch (no allocations allowed).
__device__ float4   g_part[NCH][64 * WF4];  // per-chunk GEMV partials (1 MB)
__device__ float    g_x[H];
__device__ unsigned g_bar[NPH];             // monotonic barrier counters

// ---------------------------------------------------------------------------
// Software grid barrier. Ticket-based, counters monotonically increase across
// graph replays (no reset -> no reset race). Tickets of one launch occupy one
// contiguous NB-window, so target = floor(ticket/NB)*NB + NB.
// ---------------------------------------------------------------------------
__device__ __forceinline__ void grid_bar(int p) {
    __syncthreads();
    if (threadIdx.x == 0) {
        __threadfence();
        unsigned ticket = atomicAdd(&g_bar[p], 1u);
        unsigned target = (ticket / NB) * NB + NB;
        volatile unsigned* ctr = &g_bar[p];
        while (*ctr < target) __nanosleep(64);
        __threadfence();
    }
    __syncthreads();
}

__device__ __forceinline__ float4 f4add(float4 a, float4 b) {
    return make_float4(a.x + b.x, a.y + b.y, a.z + b.z, a.w + b.w);
}

// ---------------------------------------------------------------------------
// One persistent kernel. Per column-chunk c (1024 cols):
//  A : 512 blocks = 64 k-stripes x 8 col-groups compute GEMV partials.
//  A2: blocks 0..255 finish x for the chunk (partog sum + i2h + bias + relu).
//  B : all blocks do the hebb update for the chunk; hebb slice is L2-hot
//      (read in A, <126 MB of traffic in between). Last chunk: blocks 0..63
//      also compute the output head.
// ---------------------------------------------------------------------------
__global__ void __launch_bounds__(256, 4)
k_fused(const float* __restrict__ inp,    const float* __restrict__ hidden,
        const float* __restrict__ hebb,   const float* __restrict__ W_i2h,
        const float* __restrict__ b_i2h,  const float* __restrict__ w,
        const float* __restrict__ plas,   const float* __restrict__ learn_p,
        const float* __restrict__ W_h2o,  const float* __restrict__ b_h2o,
        float* __restrict__ out, float* __restrict__ x_out,
        float* __restrict__ hebb_out) {
    __shared__ float4 sp[16][32];   // A: [kgroup][f4col_local]; B: out-head red
    __shared__ float4 stot;
    __shared__ float  sdot[4];

    int b = blockIdx.x;
    int t = threadIdx.x;
    const float4* w4 = (const float4*)w;
    const float4* p4 = (const float4*)plas;
    const float4* h4 = (const float4*)hebb;
    const float4* x4 = (const float4*)g_x;
    float learn = __ldg(learn_p);
    float am    = 1.f - learn;

    for (int c = 0; c < NCH; ++c) {
        // ================= Phase A: GEMV partials =================
        {
            int ks = b >> 3;           // k-stripe 0..63 (64 rows each)
            int cg = b & 7;            // col-group 0..7 (32 f4 each)
            int f8 = t & 15;           // 16 f8-cols per group
            int kg = t >> 4;           // 16 k-subgroups (4 rows each)
            int krow = ks * 64 + kg * 4;
            size_t fcol = (size_t)c * WF4 + cg * 32 + f8 * 2;

            float4 acc0 = make_float4(0.f, 0.f, 0.f, 0.f);
            float4 acc1 = make_float4(0.f, 0.f, 0.f, 0.f);
            size_t idx = (size_t)krow * NJ4 + fcol;
#pragma unroll
            for (int r = 0; r < 4; ++r, idx += NJ4) {
                float hk = __ldg(hidden + krow + r);
                float4 a0 = w4[idx],  a1 = w4[idx + 1];
                float4 b0 = p4[idx],  b1 = p4[idx + 1];
                float4 c0 = h4[idx],  c1 = h4[idx + 1];
                acc0.x += hk * fmaf(b0.x, c0.x, a0.x);
                acc0.y += hk * fmaf(b0.y, c0.y, a0.y);
                acc0.z += hk * fmaf(b0.z, c0.z, a0.z);
                acc0.w += hk * fmaf(b0.w, c0.w, a0.w);
                acc1.x += hk * fmaf(b1.x, c1.x, a1.x);
                acc1.y += hk * fmaf(b1.y, c1.y, a1.y);
                acc1.z += hk * fmaf(b1.z, c1.z, a1.z);
                acc1.w += hk * fmaf(b1.w, c1.w, a1.w);
            }
            sp[kg][f8 * 2]     = acc0;
            sp[kg][f8 * 2 + 1] = acc1;
            __syncthreads();
            if (t < 32) {
                float4 s = make_float4(0.f, 0.f, 0.f, 0.f);
#pragma unroll
                for (int g = 0; g < 16; ++g) s = f4add(s, sp[g][t]);
                g_part[c][ks * WF4 + cg * 32 + t] = s;
            }
        }
        grid_bar(2 * c);

        // ================= Phase A2: finish x for chunk =================
        if (b < WF4) {                       // one f4-column per block
            int lane = t & 31, wrp = t >> 5;
            if (wrp == 0) {
                // sum 64 stripe partials (strided, L2-hot)
                float4 s = f4add(g_part[c][lane * WF4 + b],
                                 g_part[c][(lane + 32) * WF4 + b]);
#pragma unroll
                for (int o = 16; o; o >>= 1) {
                    s.x += __shfl_down_sync(0xffffffffu, s.x, o);
                    s.y += __shfl_down_sync(0xffffffffu, s.y, o);
                    s.z += __shfl_down_sync(0xffffffffu, s.z, o);
                    s.w += __shfl_down_sync(0xffffffffu, s.w, o);
                }
                if (lane == 0) stot = s;
            } else if (wrp <= 4) {
                // i2h dot for scalar col jj
                int jj = wrp - 1;
                int jglob = (c * WF4 + b) * 4 + jj;
                const float4* row = (const float4*)(W_i2h + (size_t)jglob * IN);
                const float4* in4 = (const float4*)inp;
                float d = 0.f;
#pragma unroll
                for (int q = 0; q < (IN / 4) / 32; ++q) {
                    float4 aa = row[lane + q * 32];
                    float4 bb = in4[lane + q * 32];
                    d += aa.x * bb.x + aa.y * bb.y + aa.z * bb.z + aa.w * bb.w;
                }
#pragma unroll
                for (int o = 16; o; o >>= 1)
                    d += __shfl_down_sync(0xffffffffu, d, o);
                if (lane == 0) sdot[jj] = d;
            }
            __syncthreads();
            if (t < 4) {
                float base = (t == 0) ? stot.x : (t == 1) ? stot.y
                           : (t == 2) ? stot.z : stot.w;
                int jglob = (c * WF4 + b) * 4 + t;
                float v = fmaxf(base + sdot[t] + b_i2h[jglob], 0.f);
                g_x[jglob]   = v;
                x_out[jglob] = v;
            }
        }
        grid_bar(2 * c + 1);

        // ================= Phase B =================
        if (c == NCH - 1 && b < OUT) {
            // output head: out[b] = tanh(dot(x, W_h2o[b,:]) + bias)
            const float4* wr = (const float4*)(W_h2o + (size_t)b * H);
            float acc = 0.f;
#pragma unroll
            for (int q = 0; q < NJ4 / 256; ++q) {
                float4 aa = wr[t + q * 256];
                float4 bb = x4[t + q * 256];
                acc += aa.x * bb.x + aa.y * bb.y + aa.z * bb.z + aa.w * bb.w;
            }
#pragma unroll
            for (int o = 16; o; o >>= 1)
                acc += __shfl_down_sync(0xffffffffu, acc, o);
            if ((t & 31) == 0) ((float*)sp)[t >> 5] = acc;
            __syncthreads();
            if (t == 0) {
                float v = 0.f;
#pragma unroll
                for (int q = 0; q < 8; ++q) v += ((float*)sp)[q];
                out[b] = tanhf(v + b_h2o[b]);
            }
        }

        // hebb update for chunk c: block b handles rows [b*8, b*8+8)
        {
            float4 xv = x4[c * WF4 + t];     // same cols for all 8 rows
            int row0 = b * 8;
#pragma unroll
            for (int s = 0; s < 8; ++s) {
                int row = row0 + s;
                size_t gidx = (size_t)row * NJ4 + c * WF4 + t;
                float hk = __ldg(hidden + row);
                float sc = learn * hk;
                float4 hb = h4[gidx];        // expect L2 hit (read in A)
                float4 o4;
                o4.x = fmaf(am, hb.x, sc * xv.x);
                o4.y = fmaf(am, hb.y, sc * xv.y);
                o4.z = fmaf(am, hb.z, sc * xv.z);
                o4.w = fmaf(am, hb.w, sc * xv.w);
                __stcs((float4*)hebb_out + gidx, o4);
            }
        }
        // no barrier needed: B(c) and A(c+1) touch disjoint data
    }
}

// ---------------------------------------------------------------------------
// Inputs: 0 inp, 1 hidden, 2 hebb, 3 W_i2h, 4 b_i2h, 5 w, 6 plas,
//         7 learn, 8 W_h2o, 9 b_h2o
// Output: [out(64) | x(4096) | hebb_new(16777216)]
// ---------------------------------------------------------------------------
extern "C" void kernel_launch(void* const* d_in, const int* in_sizes, int n_in,
                              void* d_out, int out_size) {
    const float* inp    = (const float*)d_in[0];
    const float* hidden = (const float*)d_in[1];
    const float* hebb   = (const float*)d_in[2];
    const float* W_i2h  = (const float*)d_in[3];
    const float* b_i2h  = (const float*)d_in[4];
    const float* w      = (const float*)d_in[5];
    const float* plas   = (const float*)d_in[6];
    const float* learn  = (const float*)d_in[7];
    const float* W_h2o  = (const float*)d_in[8];
    const float* b_h2o  = (const float*)d_in[9];

    float* out      = (float*)d_out;
    float* x_out    = out + OUT;
    float* hebb_out = out + OUT + H;

    k_fused<<<NB, 256>>>(inp, hidden, hebb, W_i2h, b_i2h, w, plas, learn,
                         W_h2o, b_h2o, out, x_out, hebb_out);
}